// round 10
// baseline (speedup 1.0000x reference)
#include <cuda_runtime.h>
#include <math.h>
#include <stdint.h>

#define ND   64
#define ED   32
#define HID  256
#define MSGD 128
#define MAX_EDGES 800000
#define MAX_NODES 50000

#define BM    64      // tile: 64 edges / nodes / agents
#define HPAD  260     // *4B = 1040, 16B multiple
#define EPAD  36
#define APAD  68
#define XPAD  132
#define PROJW 512     // [Ps(256) | Pr(256)] per node

typedef unsigned long long u64;

// ---- packed f32x2 helpers (sm_103a FFMA2 path) ----
__device__ __forceinline__ u64 ffma2(u64 a, u64 b, u64 c) {
    u64 d;
    asm("fma.rn.f32x2 %0, %1, %2, %3;" : "=l"(d) : "l"(a), "l"(b), "l"(c));
    return d;
}
__device__ __forceinline__ u64 pack2(float x) {
    u64 r;
    asm("mov.b64 %0, {%1, %1};" : "=l"(r) : "f"(x));
    return r;
}
__device__ __forceinline__ float2 unpack2(u64 v) {
    float2 f;
    asm("mov.b64 {%0, %1}, %2;" : "=f"(f.x), "=f"(f.y) : "l"(v));
    return f;
}
__device__ __forceinline__ void red_add_v4(float* p, float4 v) {
    asm volatile("red.global.add.v4.f32 [%0], {%1, %2, %3, %4};"
                 :: "l"(p), "f"(v.x), "f"(v.y), "f"(v.z), "f"(v.w) : "memory");
}

// ---- scratch ----
__device__ int   g_count;
__device__ int   g_active[MAX_EDGES];
__device__ int   g_crecv[MAX_EDGES];
__device__ float g_denom[MAX_NODES];
__device__ float g_aggr[(size_t)MAX_NODES * MSGD];
__device__ float g_proj[(size_t)MAX_NODES * PROJW];

// ---------------- init ----------------
__global__ void init_kernel(int n_agents) {
    int i = blockIdx.x * blockDim.x + threadIdx.x;
    int total = n_agents * MSGD;
    if (i < total) g_aggr[i] = 0.f;
    if (i < n_agents) g_denom[i] = 0.f;
    if (i == 0) g_count = 0;
}

// ---------------- compact ----------------
__global__ void compact_kernel(const int* __restrict__ recv, int n_edges, int n_agents) {
    int i = blockIdx.x * blockDim.x + threadIdx.x;
    if (i >= n_edges) return;
    int r = recv[i];
    if (r < n_agents) {
        int p = atomicAdd(&g_count, 1);
        g_active[p] = i;
        g_crecv[p]  = r;
    }
}

// Warp/lane mapping used by all GEMMs below (256 threads = 8 warps):
//   rg = ty>>1 (4 row-groups of 16 rows), cs = ty&1 (2 column-halves)
//   lg = tx&15 (col-group), hf = tx>>4 (row-half of 8 rows)
// Lanes 0-15 and 16-31 read IDENTICAL weight addresses -> coalescer halves
// weight bytes per warp; each weight column-half is read by 4 warps not 8.

// ---------------- node projections: P = node_feats @ [W1_s | W1_r] ----------
__global__ __launch_bounds__(256, 2) void node_proj_kernel(
    const float* __restrict__ node_feats, const float* __restrict__ W1,
    int n_nodes, int n_agents)
{
    __shared__ float s_a[BM][APAD];
    const int r0 = blockIdx.x * BM;
    const int by = blockIdx.y;
    const int lim = (by == 0) ? n_nodes : n_agents;
    if (r0 >= lim) return;
    const int tid = threadIdx.x;

    for (int idx = tid; idx < BM * 16; idx += 256) {
        int m = idx >> 4, p = idx & 15;
        int row = r0 + m;
        float4 v = make_float4(0.f, 0.f, 0.f, 0.f);
        if (row < lim) v = ((const float4*)(node_feats + (size_t)row * ND))[p];
        *(float4*)&s_a[m][p * 4] = v;
    }
    __syncthreads();

    const int tx = tid & 31, ty = tid >> 5;
    const int rbase = (ty >> 1) * 16 + (tx >> 4) * 8;
    const int n1 = (ty & 1) * 128 + (tx & 15) * 8;
    const float* Wblk = W1 + (size_t)(by * 64) * HID;

    u64 acc[8][4];
    #pragma unroll
    for (int i = 0; i < 8; i++)
        #pragma unroll
        for (int p = 0; p < 4; p++) acc[i][p] = 0ull;

    for (int k = 0; k < 64; k += 4) {
        float av[8][4];
        #pragma unroll
        for (int i = 0; i < 8; i++)
            *(float4*)av[i] = *(const float4*)&s_a[rbase + i][k];
        #pragma unroll
        for (int kk = 0; kk < 4; kk++) {
            const ulonglong2* wp = (const ulonglong2*)(Wblk + (k + kk) * HID + n1);
            ulonglong2 w01 = wp[0], w23 = wp[1];
            u64 w[4] = {w01.x, w01.y, w23.x, w23.y};
            #pragma unroll
            for (int i = 0; i < 8; i++) {
                u64 a = pack2(av[i][kk]);
                #pragma unroll
                for (int p = 0; p < 4; p++) acc[i][p] = ffma2(a, w[p], acc[i][p]);
            }
        }
    }
    #pragma unroll
    for (int i = 0; i < 8; i++) {
        int row = r0 + rbase + i;
        if (row < lim) {
            float* dst = g_proj + (size_t)row * PROJW + by * 256 + n1;
            #pragma unroll
            for (int g = 0; g < 2; g++) {
                float2 u0 = unpack2(acc[i][2 * g]);
                float2 u1 = unpack2(acc[i][2 * g + 1]);
                *(float4*)(dst + g * 4) = make_float4(u0.x, u0.y, u1.x, u1.y);
            }
        }
    }
}

// ---------------- fused edge MLP + softmax-free scatter ----------------------
__global__ __launch_bounds__(256, 2) void edge_mlp_kernel(
    const float* __restrict__ edge_feats,
    const float* __restrict__ W1, const float* __restrict__ b1,
    const float* __restrict__ W2, const float* __restrict__ b2,
    const float* __restrict__ w_gate, const float* __restrict__ b_gate,
    const int* __restrict__ senders)
{
    extern __shared__ float smem[];
    float (*s_e)[EPAD] = (float (*)[EPAD])smem;                  // 64 x 36
    float (*s_h)[HPAD] = (float (*)[HPAD])(smem + BM * EPAD);    // 64 x 260
    int* s_is   = (int*)(smem + BM * EPAD + BM * HPAD);
    int* s_ir   = s_is + BM;
    int* s_eidx = s_ir + BM;
    float* s_gate = (float*)(s_eidx + BM);                        // [4][2][16]

    const int cnt = g_count;
    const int e0  = blockIdx.x * BM;
    if (e0 >= cnt) return;
    const int tid = threadIdx.x;

    if (tid < BM) {
        int ci = e0 + tid;
        int e = 0, s = 0, r = 0;
        if (ci < cnt) { e = g_active[ci]; s = senders[e]; r = g_crecv[ci]; }
        s_eidx[tid] = e; s_is[tid] = s; s_ir[tid] = r;
    }
    __syncthreads();

    // pre-sum Ps + Pr into s_h (coalesced) + stage edge feats
    for (int idx = tid; idx < BM * 64; idx += 256) {
        int m = idx >> 6, p = idx & 63;
        const float4 a = *(const float4*)(g_proj + (size_t)s_is[m] * PROJW + p * 4);
        const float4 b = *(const float4*)(g_proj + (size_t)s_ir[m] * PROJW + 256 + p * 4);
        *(float4*)&s_h[m][p * 4] = make_float4(a.x + b.x, a.y + b.y, a.z + b.z, a.w + b.w);
    }
    for (int idx = tid; idx < BM * 8; idx += 256) {
        int m = idx >> 3, p = idx & 7;
        float4 v = make_float4(0.f, 0.f, 0.f, 0.f);
        if (e0 + m < cnt) v = ((const float4*)(edge_feats + (size_t)s_eidx[m] * ED))[p];
        *(float4*)&s_e[m][p * 4] = v;
    }
    __syncthreads();

    const int tx = tid & 31, ty = tid >> 5;
    const int rg = ty >> 1, cs = ty & 1;
    const int hf = tx >> 4, lg = tx & 15;
    const int rbase = rg * 16 + hf * 8;
    const int n1 = cs * 128 + lg * 8;     // GEMM1 cols
    const int c2 = cs * 64 + lg * 4;      // GEMM2 cols

    // ---- GEMM1 (edge part, K=32) + bias: per-thread 8 rows x 8 cols ----
    u64 acc[8][4];
    {
        const u64* bp = (const u64*)(b1 + n1);
        u64 bv[4] = {bp[0], bp[1], bp[2], bp[3]};
        #pragma unroll
        for (int i = 0; i < 8; i++)
            #pragma unroll
            for (int p = 0; p < 4; p++) acc[i][p] = bv[p];
    }
    const float* W1e = W1 + (size_t)(2 * ND) * HID;
    for (int k = 0; k < ED; k += 4) {
        float av[8][4];
        #pragma unroll
        for (int i = 0; i < 8; i++)
            *(float4*)av[i] = *(const float4*)&s_e[rbase + i][k];
        #pragma unroll
        for (int kk = 0; kk < 4; kk++) {
            const ulonglong2* wp = (const ulonglong2*)(W1e + (k + kk) * HID + n1);
            ulonglong2 w01 = wp[0], w23 = wp[1];
            u64 w[4] = {w01.x, w01.y, w23.x, w23.y};
            #pragma unroll
            for (int i = 0; i < 8; i++) {
                u64 a = pack2(av[i][kk]);
                #pragma unroll
                for (int p = 0; p < 4; p++) acc[i][p] = ffma2(a, w[p], acc[i][p]);
            }
        }
    }

    // h = relu(acc + presummed projections) -> s_h
    #pragma unroll
    for (int i = 0; i < 8; i++) {
        int m = rbase + i;
        #pragma unroll
        for (int g = 0; g < 2; g++) {
            float4 hv = *(float4*)&s_h[m][n1 + g * 4];
            float2 u0 = unpack2(acc[i][2 * g]);
            float2 u1 = unpack2(acc[i][2 * g + 1]);
            float4 r;
            r.x = fmaxf(u0.x + hv.x, 0.f);
            r.y = fmaxf(u0.y + hv.y, 0.f);
            r.z = fmaxf(u1.x + hv.z, 0.f);
            r.w = fmaxf(u1.y + hv.w, 0.f);
            *(float4*)&s_h[m][n1 + g * 4] = r;
        }
    }
    __syncthreads();

    // ---- GEMM2: per-thread 8 rows x 4 cols, col-halved weights ----
    u64 acc2[8][2];
    {
        const u64* bp = (const u64*)(b2 + c2);
        u64 b0 = bp[0], b1v = bp[1];
        #pragma unroll
        for (int i = 0; i < 8; i++) { acc2[i][0] = b0; acc2[i][1] = b1v; }
    }
    #pragma unroll 2
    for (int k = 0; k < HID; k += 4) {
        float av[8][4];
        #pragma unroll
        for (int i = 0; i < 8; i++)
            *(float4*)av[i] = *(const float4*)&s_h[rbase + i][k];
        #pragma unroll
        for (int kk = 0; kk < 4; kk++) {
            ulonglong2 w01 = *(const ulonglong2*)(W2 + (k + kk) * MSGD + c2);
            #pragma unroll
            for (int i = 0; i < 8; i++) {
                u64 a = pack2(av[i][kk]);
                acc2[i][0] = ffma2(a, w01.x, acc2[i][0]);
                acc2[i][1] = ffma2(a, w01.y, acc2[i][1]);
            }
        }
    }

    // relu + gate partials (16-lane reduce, then cross-warp via smem)
    float wg[4];
    *(float4*)wg = *(const float4*)(w_gate + c2);
    const float bg = b_gate[0];

    float v0[8], v1[8], v2[8], v3[8], partial[8];
    #pragma unroll
    for (int i = 0; i < 8; i++) {
        float2 u0 = unpack2(acc2[i][0]);
        float2 u1 = unpack2(acc2[i][1]);
        v0[i] = fmaxf(u0.x, 0.f); v1[i] = fmaxf(u0.y, 0.f);
        v2[i] = fmaxf(u1.x, 0.f); v3[i] = fmaxf(u1.y, 0.f);
        float s = v0[i] * wg[0];
        s = fmaf(v1[i], wg[1], s);
        s = fmaf(v2[i], wg[2], s);
        s = fmaf(v3[i], wg[3], s);
        partial[i] = s;
    }
    #pragma unroll
    for (int o = 8; o >= 1; o >>= 1) {
        #pragma unroll
        for (int i = 0; i < 8; i++)
            partial[i] += __shfl_xor_sync(0xffffffffu, partial[i], o);
    }
    if (lg == 0) {
        #pragma unroll
        for (int i = 0; i < 8; i++)
            s_gate[(rg * 2 + cs) * 16 + hf * 8 + i] = partial[i];
    }
    __syncthreads();

    #pragma unroll
    for (int i = 0; i < 8; i++) {
        int ci = e0 + rbase + i;
        if (ci < cnt) {
            float tot = s_gate[(rg * 2 + 0) * 16 + hf * 8 + i]
                      + s_gate[(rg * 2 + 1) * 16 + hf * 8 + i];
            float ev = expf(tot + bg);               // max-free softmax weight
            int r = s_ir[rbase + i];
            if (cs == 0 && lg == 0) atomicAdd(g_denom + r, ev);
            red_add_v4(g_aggr + (size_t)r * MSGD + c2,
                       make_float4(ev * v0[i], ev * v1[i], ev * v2[i], ev * v3[i]));
        }
    }
}

// ---------------- agent MLP (divides by denom on load) -----------------------
__global__ __launch_bounds__(256, 2) void agent_mlp_kernel(
    const float* __restrict__ W_h1, const float* __restrict__ b_h1,
    const float* __restrict__ W_h2, const float* __restrict__ b_h2,
    const float* __restrict__ W_out, const float* __restrict__ b_out,
    float* __restrict__ out, int n_agents)
{
    extern __shared__ float smem[];
    float (*s_x)[XPAD] = (float (*)[XPAD])smem;
    float (*s_h)[HPAD] = (float (*)[HPAD])(smem + BM * XPAD);
    float* s_gate = smem + BM * XPAD + BM * HPAD;                 // [4][2][16]

    const int r0 = blockIdx.x * BM;
    const int tid = threadIdx.x;

    for (int idx = tid; idx < BM * 32; idx += 256) {
        int m = idx >> 5, p = idx & 31;
        int r = r0 + m;
        float4 v = make_float4(0.f, 0.f, 0.f, 0.f);
        if (r < n_agents) {
            float inv = __frcp_rn(g_denom[r] + 1e-9f);
            v = *(const float4*)(g_aggr + (size_t)r * MSGD + p * 4);
            v.x *= inv; v.y *= inv; v.z *= inv; v.w *= inv;
        }
        *(float4*)&s_x[m][p * 4] = v;
    }
    __syncthreads();

    const int tx = tid & 31, ty = tid >> 5;
    const int rg = ty >> 1, cs = ty & 1;
    const int hf = tx >> 4, lg = tx & 15;
    const int rbase = rg * 16 + hf * 8;
    const int n1 = cs * 128 + lg * 8;

    u64 acc[8][4];
    {
        const u64* bp = (const u64*)(b_h1 + n1);
        u64 bv[4] = {bp[0], bp[1], bp[2], bp[3]};
        #pragma unroll
        for (int i = 0; i < 8; i++)
            #pragma unroll
            for (int p = 0; p < 4; p++) acc[i][p] = bv[p];
    }
    for (int k = 0; k < MSGD; k += 4) {
        float av[8][4];
        #pragma unroll
        for (int i = 0; i < 8; i++)
            *(float4*)av[i] = *(const float4*)&s_x[rbase + i][k];
        #pragma unroll
        for (int kk = 0; kk < 4; kk++) {
            const ulonglong2* wp = (const ulonglong2*)(W_h1 + (k + kk) * HID + n1);
            ulonglong2 w01 = wp[0], w23 = wp[1];
            u64 w[4] = {w01.x, w01.y, w23.x, w23.y};
            #pragma unroll
            for (int i = 0; i < 8; i++) {
                u64 a = pack2(av[i][kk]);
                #pragma unroll
                for (int p = 0; p < 4; p++) acc[i][p] = ffma2(a, w[p], acc[i][p]);
            }
        }
    }
    #pragma unroll
    for (int i = 0; i < 8; i++) {
        #pragma unroll
        for (int g = 0; g < 2; g++) {
            float2 u0 = unpack2(acc[i][2 * g]);
            float2 u1 = unpack2(acc[i][2 * g + 1]);
            float4 r;
            r.x = fmaxf(u0.x, 0.f); r.y = fmaxf(u0.y, 0.f);
            r.z = fmaxf(u1.x, 0.f); r.w = fmaxf(u1.y, 0.f);
            *(float4*)&s_h[rbase + i][n1 + g * 4] = r;
        }
    }
    __syncthreads();

    {
        const u64* bp = (const u64*)(b_h2 + n1);
        u64 bv[4] = {bp[0], bp[1], bp[2], bp[3]};
        #pragma unroll
        for (int i = 0; i < 8; i++)
            #pragma unroll
            for (int p = 0; p < 4; p++) acc[i][p] = bv[p];
    }
    #pragma unroll 2
    for (int k = 0; k < HID; k += 4) {
        float av[8][4];
        #pragma unroll
        for (int i = 0; i < 8; i++)
            *(float4*)av[i] = *(const float4*)&s_h[rbase + i][k];
        #pragma unroll
        for (int kk = 0; kk < 4; kk++) {
            const ulonglong2* wp = (const ulonglong2*)(W_h2 + (k + kk) * HID + n1);
            ulonglong2 w01 = wp[0], w23 = wp[1];
            u64 w[4] = {w01.x, w01.y, w23.x, w23.y};
            #pragma unroll
            for (int i = 0; i < 8; i++) {
                u64 a = pack2(av[i][kk]);
                #pragma unroll
                for (int p = 0; p < 4; p++) acc[i][p] = ffma2(a, w[p], acc[i][p]);
            }
        }
    }

    float wo[8];
    *(float4*)&wo[0] = *(const float4*)(W_out + n1);
    *(float4*)&wo[4] = *(const float4*)(W_out + n1 + 4);
    float partial[8];
    #pragma unroll
    for (int i = 0; i < 8; i++) {
        float s = 0.f;
        #pragma unroll
        for (int p = 0; p < 4; p++) {
            float2 u = unpack2(acc[i][p]);
            s = fmaf(fmaxf(u.x, 0.f), wo[2 * p], s);
            s = fmaf(fmaxf(u.y, 0.f), wo[2 * p + 1], s);
        }
        partial[i] = s;
    }
    #pragma unroll
    for (int o = 8; o >= 1; o >>= 1) {
        #pragma unroll
        for (int i = 0; i < 8; i++)
            partial[i] += __shfl_xor_sync(0xffffffffu, partial[i], o);
    }
    if (lg == 0) {
        #pragma unroll
        for (int i = 0; i < 8; i++)
            s_gate[(rg * 2 + cs) * 16 + hf * 8 + i] = partial[i];
    }
    __syncthreads();

    if (cs == 0 && lg == 0) {
        float bo = b_out[0];
        #pragma unroll
        for (int i = 0; i < 8; i++) {
            int r = r0 + rbase + i;
            if (r < n_agents) {
                float tot = s_gate[(rg * 2 + 0) * 16 + hf * 8 + i]
                          + s_gate[(rg * 2 + 1) * 16 + hf * 8 + i];
                out[r] = tanhf(tot + bo);
            }
        }
    }
}

// ---------------------------------------------------------------------------
extern "C" void kernel_launch(void* const* d_in, const int* in_sizes, int n_in,
                              void* d_out, int out_size) {
    const float* node_feats = (const float*)d_in[0];
    const float* edge_feats = (const float*)d_in[1];
    const float* W_msg1 = (const float*)d_in[2];
    const float* b_msg1 = (const float*)d_in[3];
    const float* W_msg2 = (const float*)d_in[4];
    const float* b_msg2 = (const float*)d_in[5];
    const float* w_gate = (const float*)d_in[6];
    const float* b_gate = (const float*)d_in[7];
    const float* W_h1   = (const float*)d_in[8];
    const float* b_h1   = (const float*)d_in[9];
    const float* W_h2   = (const float*)d_in[10];
    const float* b_h2   = (const float*)d_in[11];
    const float* W_out  = (const float*)d_in[12];
    const float* b_out  = (const float*)d_in[13];
    const int* senders   = (const int*)d_in[14];
    const int* receivers = (const int*)d_in[15];
    float* out = (float*)d_out;

    const int n_edges  = in_sizes[14];
    const int n_nodes  = in_sizes[0] / ND;
    const int n_agents = out_size;

    const int SMEM_EDGE  = (BM * EPAD + BM * HPAD) * (int)sizeof(float)
                         + 3 * BM * (int)sizeof(int) + 128 * (int)sizeof(float);
    const int SMEM_AGENT = (BM * XPAD + BM * HPAD) * (int)sizeof(float)
                         + 128 * (int)sizeof(float);
    cudaFuncSetAttribute(edge_mlp_kernel, cudaFuncAttributeMaxDynamicSharedMemorySize, SMEM_EDGE);
    cudaFuncSetAttribute(agent_mlp_kernel, cudaFuncAttributeMaxDynamicSharedMemorySize, SMEM_AGENT);

    {
        int total = n_agents * MSGD;
        init_kernel<<<(total + 255) / 256, 256>>>(n_agents);
    }
    compact_kernel<<<(n_edges + 255) / 256, 256>>>(receivers, n_edges, n_agents);
    {
        dim3 grid((n_nodes + BM - 1) / BM, 2);
        node_proj_kernel<<<grid, 256>>>(node_feats, W_msg1, n_nodes, n_agents);
    }
    {
        int grid = (n_edges + BM - 1) / BM;
        edge_mlp_kernel<<<grid, 256, SMEM_EDGE>>>(
            edge_feats, W_msg1, b_msg1, W_msg2, b_msg2, w_gate, b_gate, senders);
    }
    agent_mlp_kernel<<<(n_agents + BM - 1) / BM, 256, SMEM_AGENT>>>(
        W_h1, b_h1, W_h2, b_h2, W_out, b_out, out, n_agents);
}